// round 1
// baseline (speedup 1.0000x reference)
#include <cuda_runtime.h>
#include <math.h>

#define BB 32
#define DD 1024
#define HH 64
#define OO 1000
#define EE 6

// Scratch (no allocations allowed in kernel_launch)
__device__ float g_gates[BB * EE];
__device__ float g_h[EE * BB * HH];

// ---------------------------------------------------------------------------
// Kernel 1: gate logits -> top-2 softmax -> dense gates; also zero the output
// 1 block, 1024 threads (32 warps). 192 (b,e) dot products of length 1024:
// each warp handles 6 tasks, lanes stride D by 32, shfl reduce.
// ---------------------------------------------------------------------------
__global__ void gate_kernel(const float* __restrict__ x,
                            const float* __restrict__ gw,
                            const float* __restrict__ gb,
                            float* __restrict__ out) {
    __shared__ float logits[BB][EE];
    const int tid  = threadIdx.x;
    const int warp = tid >> 5;
    const int lane = tid & 31;

    // Zero the output buffer (combine kernel accumulates with atomics)
    for (int i = tid; i < BB * OO; i += 1024) out[i] = 0.0f;

    // 192 tasks over 32 warps: task p = warp*6 + j
    #pragma unroll
    for (int j = 0; j < 6; ++j) {
        int p = warp * 6 + j;          // 0..191
        int b = p & 31;                // p % 32
        int e = p >> 5;                // p / 32
        const float* xr = x + b * DD;
        float s = 0.0f;
        #pragma unroll 8
        for (int i = 0; i < DD / 32; ++i) {
            int d = lane + 32 * i;
            s += xr[d] * gw[d * EE + e];
        }
        #pragma unroll
        for (int off = 16; off > 0; off >>= 1)
            s += __shfl_down_sync(0xFFFFFFFFu, s, off);
        if (lane == 0) logits[b][e] = s + gb[e];
    }
    __syncthreads();

    // Per-row top-2 + softmax over the two selected logits
    if (tid < BB) {
        float v[EE];
        #pragma unroll
        for (int e = 0; e < EE; ++e) v[e] = logits[tid][e];

        int i1 = 0; float m1 = v[0];
        #pragma unroll
        for (int e = 1; e < EE; ++e) if (v[e] > m1) { m1 = v[e]; i1 = e; }
        int i2 = -1; float m2 = -INFINITY;
        #pragma unroll
        for (int e = 0; e < EE; ++e) if (e != i1 && v[e] > m2) { m2 = v[e]; i2 = e; }

        // softmax over {m1, m2}, m1 >= m2 so exp arg <= 0 (stable)
        float g1 = 1.0f / (1.0f + expf(m2 - m1));
        float g2 = 1.0f - g1;

        #pragma unroll
        for (int e = 0; e < EE; ++e) g_gates[tid * EE + e] = 0.0f;
        g_gates[tid * EE + i1] = g1;
        g_gates[tid * EE + i2] = g2;
    }
}

// ---------------------------------------------------------------------------
// Kernel 2: h[e,b,:] = relu(x[b] @ w1[e] + b1[e]) for selected (e,b) only.
// Grid (E, 8): expert x 8-column chunk. 256 threads.
// Thread task = (selected-row, col-within-chunk); full 1024-length dot each.
// 8 adjacent cols -> one 32B w1 sector per d; identical across rows -> L1 hit.
// ---------------------------------------------------------------------------
__global__ void h_kernel(const float* __restrict__ x,
                         const float* __restrict__ w1,
                         const float* __restrict__ b1) {
    const int e  = blockIdx.x;
    const int cb = blockIdx.y * 8;     // column base, chunk of 8

    __shared__ int sel[BB];
    __shared__ int nsel_s;
    const int tid = threadIdx.x;

    if (tid == 0) {
        int n = 0;
        for (int b = 0; b < BB; ++b)
            if (g_gates[b * EE + e] != 0.0f) sel[n++] = b;
        nsel_s = n;
    }
    __syncthreads();
    const int n = nsel_s;

    for (int t = tid; t < n * 8; t += 256) {
        const int r   = t >> 3;
        const int c   = t & 7;
        const int b   = sel[r];
        const int col = cb + c;
        const float* xr = x + b * DD;
        const float* wc = w1 + (size_t)e * DD * HH + col;

        float a0 = 0.f, a1 = 0.f, a2 = 0.f, a3 = 0.f;
        #pragma unroll 4
        for (int d = 0; d < DD; d += 4) {
            a0 += xr[d + 0] * wc[(d + 0) * HH];
            a1 += xr[d + 1] * wc[(d + 1) * HH];
            a2 += xr[d + 2] * wc[(d + 2) * HH];
            a3 += xr[d + 3] * wc[(d + 3) * HH];
        }
        float s = (a0 + a1) + (a2 + a3) + b1[e * HH + col];
        g_h[((e * BB) + b) * HH + col] = fmaxf(s, 0.0f);
    }
}

// ---------------------------------------------------------------------------
// Kernel 3: out[b,:] += g[b,e] * (h[e,b,:] @ w2[e] + b2[e]) for selected rows.
// Grid (E, 8): expert x 125-output chunk. 128 threads, one output col each.
// w2 chunk (32KB) read once per block, L1-resident across rows.
// Exactly 2 atomic adds land on each out element -> commutative -> determinate.
// ---------------------------------------------------------------------------
__global__ void combine_kernel(const float* __restrict__ w2,
                               const float* __restrict__ b2,
                               float* __restrict__ out) {
    const int e  = blockIdx.x;
    const int ob = blockIdx.y * 125;

    __shared__ int   sel[BB];
    __shared__ float gsel[BB];
    __shared__ int   nsel_s;
    __shared__ float hs[BB][HH];       // 8 KB max

    const int tid = threadIdx.x;
    if (tid == 0) {
        int n = 0;
        for (int b = 0; b < BB; ++b) {
            float g = g_gates[b * EE + e];
            if (g != 0.0f) { sel[n] = b; gsel[n] = g; ++n; }
        }
        nsel_s = n;
    }
    __syncthreads();
    const int n = nsel_s;

    // Stage selected h rows into shared memory (coalesced)
    for (int i = tid; i < n * HH; i += 128) {
        int r = i >> 6, k = i & 63;
        hs[r][k] = g_h[((e * BB) + sel[r]) * HH + k];
    }
    __syncthreads();

    if (tid < 125) {
        const int o = ob + tid;
        const float bias = b2[e * OO + o];
        const float* w2c = w2 + (size_t)e * HH * OO + o;
        for (int r = 0; r < n; ++r) {
            float acc0 = 0.f, acc1 = 0.f;
            #pragma unroll 8
            for (int k = 0; k < HH; k += 2) {
                acc0 += hs[r][k]     * w2c[k * OO];
                acc1 += hs[r][k + 1] * w2c[(k + 1) * OO];
            }
            atomicAdd(&out[sel[r] * OO + o], gsel[r] * ((acc0 + acc1) + bias));
        }
    }
}

// ---------------------------------------------------------------------------
// Inputs (metadata order): x, gate_w, gate_b, w1, b1, w2, b2. Output: f32 [32,1000]
// ---------------------------------------------------------------------------
extern "C" void kernel_launch(void* const* d_in, const int* in_sizes, int n_in,
                              void* d_out, int out_size) {
    const float* x   = (const float*)d_in[0];
    const float* gw  = (const float*)d_in[1];
    const float* gb  = (const float*)d_in[2];
    const float* w1  = (const float*)d_in[3];
    const float* b1  = (const float*)d_in[4];
    const float* w2  = (const float*)d_in[5];
    const float* b2  = (const float*)d_in[6];
    float* out = (float*)d_out;

    gate_kernel<<<1, 1024>>>(x, gw, gb, out);
    h_kernel<<<dim3(EE, 8), 256>>>(x, w1, b1);
    combine_kernel<<<dim3(EE, 8), 128>>>(w2, b2, out);
}

// round 2
// speedup vs baseline: 4.9248x; 4.9248x over previous
#include <cuda_runtime.h>
#include <math.h>

#define BB 32
#define DD 1024
#define HH 64
#define OO 1000
#define EE 6

// Scratch: per (row, top-k slot): gate-scaled hidden vector, gate weight, expert id
__device__ float g_h[BB * 2 * HH];
__device__ float g_gwt[BB * 2];
__device__ int   g_ge[BB * 2];

// ---------------------------------------------------------------------------
// Kernel 1: fused gate + expert fc1.
// Grid (BB, 2) = (row b, top-k slot k). 256 threads.
//  - stage x[b] (4KB) in smem
//  - warps 0..5 compute the 6 gate logits (lane-strided, shfl reduce)
//  - all threads redundantly compute top-2 + 2-way softmax (cheap, no divergence)
//  - h: thread (grp = tid/64, c = tid%64) accumulates d-range [256*grp, 256*grp+256)
//    of column c; coalesced w1 reads (lanes -> consecutive cols); 4-acc ILP split
//  - h pre-scaled by gate weight; expert id + gate stored for the combine kernel
// ---------------------------------------------------------------------------
__global__ void __launch_bounds__(256) h_kernel(const float* __restrict__ x,
                                                const float* __restrict__ gw,
                                                const float* __restrict__ gb,
                                                const float* __restrict__ w1,
                                                const float* __restrict__ b1) {
    const int b = blockIdx.x;
    const int k = blockIdx.y;           // 0 = top-1 expert, 1 = top-2 expert
    const int tid  = threadIdx.x;
    const int warp = tid >> 5;
    const int lane = tid & 31;

    __shared__ float xs[DD];
    __shared__ float logit[EE];
    __shared__ float part[4][HH];

    // Stage x row
    for (int i = tid; i < DD; i += 256) xs[i] = x[b * DD + i];
    __syncthreads();

    // Gate logits: warp w computes expert w
    if (warp < EE) {
        float s = 0.0f;
        #pragma unroll 8
        for (int i = lane; i < DD; i += 32) s += xs[i] * gw[i * EE + warp];
        #pragma unroll
        for (int off = 16; off > 0; off >>= 1)
            s += __shfl_down_sync(0xFFFFFFFFu, s, off);
        if (lane == 0) logit[warp] = s + gb[warp];
    }
    __syncthreads();

    // Top-2 + softmax (all threads, redundant, branch-free-ish)
    float v[EE];
    #pragma unroll
    for (int e = 0; e < EE; ++e) v[e] = logit[e];
    int i1 = 0; float m1 = v[0];
    #pragma unroll
    for (int e = 1; e < EE; ++e) if (v[e] > m1) { m1 = v[e]; i1 = e; }
    int i2 = -1; float m2 = -INFINITY;
    #pragma unroll
    for (int e = 0; e < EE; ++e) if (e != i1 && v[e] > m2) { m2 = v[e]; i2 = e; }
    const float g1 = 1.0f / (1.0f + expf(m2 - m1));   // m1 >= m2: stable
    const float gk = (k == 0) ? g1 : (1.0f - g1);
    const int   e  = (k == 0) ? i1 : i2;

    if (tid == 0) { g_gwt[b * 2 + k] = gk; g_ge[b * 2 + k] = e; }

    // fc1: 4 d-groups x 64 cols
    const int grp = tid >> 6;
    const int c   = tid & 63;
    const float* wp = w1 + ((size_t)e * DD + grp * 256) * HH + c;
    const float* xp = xs + grp * 256;

    float a0 = 0.f, a1 = 0.f, a2 = 0.f, a3 = 0.f;
    #pragma unroll 8
    for (int d = 0; d < 256; d += 4) {
        a0 += xp[d + 0] * wp[(d + 0) * HH];
        a1 += xp[d + 1] * wp[(d + 1) * HH];
        a2 += xp[d + 2] * wp[(d + 2) * HH];
        a3 += xp[d + 3] * wp[(d + 3) * HH];
    }
    part[grp][c] = (a0 + a1) + (a2 + a3);
    __syncthreads();

    if (tid < HH) {
        float s = part[0][tid] + part[1][tid] + part[2][tid] + part[3][tid]
                + b1[e * HH + tid];
        g_h[(b * 2 + k) * HH + tid] = gk * fmaxf(s, 0.0f);   // gate pre-applied
    }
}

// ---------------------------------------------------------------------------
// Kernel 2: combine. Grid (BB, 4) = (row, 250-wide O chunk). 256 threads.
// Each thread owns one output column: sums the row's two experts' fc2 dots
// (h already gate-scaled) + gate-weighted biases. Direct store: no atomics,
// no zero-init needed.
// ---------------------------------------------------------------------------
__global__ void __launch_bounds__(256) combine_kernel(const float* __restrict__ w2,
                                                      const float* __restrict__ b2,
                                                      float* __restrict__ out) {
    const int b  = blockIdx.x;
    const int oc = blockIdx.y;
    const int tid = threadIdx.x;

    __shared__ float hs[2 * HH];
    __shared__ float gwk[2];
    __shared__ int   ek[2];

    if (tid < 2 * HH) hs[tid] = g_h[b * 2 * HH + tid];
    if (tid < 2) { gwk[tid] = g_gwt[b * 2 + tid]; ek[tid] = g_ge[b * 2 + tid]; }
    __syncthreads();

    if (tid < 250) {
        const int o  = oc * 250 + tid;
        const int e0 = ek[0], e1 = ek[1];
        const float* w20 = w2 + (size_t)e0 * HH * OO + o;
        const float* w21 = w2 + (size_t)e1 * HH * OO + o;

        float a0 = 0.f, a1 = 0.f, a2 = 0.f, a3 = 0.f;
        #pragma unroll
        for (int j = 0; j < HH; j += 2) {
            a0 += hs[j]          * w20[(j)     * OO];
            a1 += hs[j + 1]      * w20[(j + 1) * OO];
            a2 += hs[HH + j]     * w21[(j)     * OO];
            a3 += hs[HH + j + 1] * w21[(j + 1) * OO];
        }
        out[b * OO + o] = (a0 + a1) + (a2 + a3)
                        + gwk[0] * b2[e0 * OO + o]
                        + gwk[1] * b2[e1 * OO + o];
    }
}

// ---------------------------------------------------------------------------
// Inputs: x, gate_w, gate_b, w1, b1, w2, b2. Output: f32 [32,1000]
// ---------------------------------------------------------------------------
extern "C" void kernel_launch(void* const* d_in, const int* in_sizes, int n_in,
                              void* d_out, int out_size) {
    const float* x  = (const float*)d_in[0];
    const float* gw = (const float*)d_in[1];
    const float* gb = (const float*)d_in[2];
    const float* w1 = (const float*)d_in[3];
    const float* b1 = (const float*)d_in[4];
    const float* w2 = (const float*)d_in[5];
    const float* b2 = (const float*)d_in[6];
    float* out = (float*)d_out;

    h_kernel<<<dim3(BB, 2), 256>>>(x, gw, gb, w1, b1);
    combine_kernel<<<dim3(BB, 4), 256>>>(w2, b2, out);
}

// round 4
// speedup vs baseline: 5.6051x; 1.1381x over previous
#include <cuda_runtime.h>
#include <math.h>

#define BB 32
#define DD 1024
#define HH 64
#define OO 1000
#define EE 6
#define NBLK (BB * 2)       // 64 blocks: (row, top-k slot)
#define NTHR 512

// Scratch + grid barrier (monotonic counter, never reset: wrap-safe)
__device__ float        g_h[BB * 2 * HH];    // gate-pre-scaled hidden
__device__ float        g_gw2[BB * 2];
__device__ int          g_ge2[BB * 2];
__device__ unsigned int g_bar;               // zero-initialized

#define FMA4(acc, v, w) do { (acc).x += (v)*(w).x; (acc).y += (v)*(w).y; \
                             (acc).z += (v)*(w).z; (acc).w += (v)*(w).w; } while (0)

__global__ void __launch_bounds__(NTHR) moe_fused(const float* __restrict__ x,
                                                  const float* __restrict__ gw,
                                                  const float* __restrict__ gb,
                                                  const float* __restrict__ w1,
                                                  const float* __restrict__ b1,
                                                  const float* __restrict__ w2,
                                                  const float* __restrict__ b2,
                                                  float* __restrict__ out) {
    const int bid = blockIdx.x;
    const int tid = threadIdx.x;
    const int warp = tid >> 5, lane = tid & 31;

    // 16B alignment REQUIRED: these are accessed via float4
    __shared__ __align__(16) float xs[DD];          // 4 KB
    __shared__ __align__(16) float part[32][HH];    // 8 KB
    __shared__ __align__(16) float hs[2 * HH];
    __shared__ float logit[EE];
    __shared__ float gks[2];
    __shared__ int   eks[2];

    // ================= PHASE 1: gate + fc1 for (b, k) = (bid>>1, bid&1) ======
    const int b = bid >> 1, k = bid & 1;

    if (tid < DD / 4)
        ((float4*)xs)[tid] = ((const float4*)(x + b * DD))[tid];
    __syncthreads();

    // gate logits: warp w -> expert w
    if (warp < EE) {
        float s = 0.0f;
        #pragma unroll 8
        for (int i = lane; i < DD; i += 32) s += xs[i] * gw[i * EE + warp];
        #pragma unroll
        for (int off = 16; off > 0; off >>= 1)
            s += __shfl_down_sync(0xFFFFFFFFu, s, off);
        if (lane == 0) logit[warp] = s + gb[warp];
    }
    __syncthreads();

    // top-2 + 2-way softmax (redundant per thread, cheap)
    float v[EE];
    #pragma unroll
    for (int e = 0; e < EE; ++e) v[e] = logit[e];
    int i1 = 0; float m1 = v[0];
    #pragma unroll
    for (int e = 1; e < EE; ++e) if (v[e] > m1) { m1 = v[e]; i1 = e; }
    int i2 = -1; float m2 = -INFINITY;
    #pragma unroll
    for (int e = 0; e < EE; ++e) if (e != i1 && v[e] > m2) { m2 = v[e]; i2 = e; }
    const float g1 = 1.0f / (1.0f + expf(m2 - m1));     // m1 >= m2: stable
    const float gk = (k == 0) ? g1 : (1.0f - g1);
    const int   e  = (k == 0) ? i1 : i2;
    if (tid == 0) { g_gw2[bid] = gk; g_ge2[bid] = e; }

    // fc1: dg = tid>>4 (32 d-groups of 32), cg = tid&15 (4 cols each), float4 loads
    {
        const int dg = tid >> 4, cg = tid & 15;
        const float* wbase = w1 + ((size_t)e * DD + dg * 32) * HH + cg * 4;
        const float* xp = xs + dg * 32;
        float4 a0 = {0,0,0,0}, a1 = {0,0,0,0}, a2 = {0,0,0,0}, a3 = {0,0,0,0};
        #pragma unroll
        for (int d = 0; d < 32; d += 4) {
            float4 w;
            w = *(const float4*)(wbase + (d + 0) * HH); FMA4(a0, xp[d + 0], w);
            w = *(const float4*)(wbase + (d + 1) * HH); FMA4(a1, xp[d + 1], w);
            w = *(const float4*)(wbase + (d + 2) * HH); FMA4(a2, xp[d + 2], w);
            w = *(const float4*)(wbase + (d + 3) * HH); FMA4(a3, xp[d + 3], w);
        }
        float4 t;
        t.x = (a0.x + a1.x) + (a2.x + a3.x);
        t.y = (a0.y + a1.y) + (a2.y + a3.y);
        t.z = (a0.z + a1.z) + (a2.z + a3.z);
        t.w = (a0.w + a1.w) + (a2.w + a3.w);
        *(float4*)&part[dg][cg * 4] = t;
    }
    __syncthreads();

    if (tid < HH) {
        float s = 0.0f;
        #pragma unroll
        for (int dg = 0; dg < 32; ++dg) s += part[dg][tid];
        s += b1[e * HH + tid];
        g_h[bid * HH + tid] = gk * fmaxf(s, 0.0f);      // gate pre-applied
    }

    // ================= GRID BARRIER (all 64 blocks resident) =================
    __threadfence();              // publish this block's g_h/g_gw2/g_ge2 writes
    __syncthreads();
    if (tid == 0) {
        unsigned old = atomicAdd(&g_bar, 1u);
        unsigned target = ((old >> 6) + 1u) << 6;       // next multiple of 64
        while ((int)(atomicAdd(&g_bar, 0u) - target) < 0) {}
    }
    __syncthreads();
    __threadfence();              // acquire before reading peers' writes

    // ================= PHASE 2: fc2 + combine for (b, half) ==================
    const int rb = bid >> 1, half = bid & 1;            // 500 o-cols per block

    if (tid < 2 * HH) hs[tid] = g_h[rb * 2 * HH + tid];
    if (tid < 2) { gks[tid] = g_gw2[rb * 2 + tid]; eks[tid] = g_ge2[rb * 2 + tid]; }
    __syncthreads();

    const int g  = tid >> 2;                            // float4 group 0..127
    const int s  = tid & 3;                             // k-quarter (16 k each)
    const int gg = (g < 125) ? g : 124;                 // clamp for safe loads
    const int o  = half * 500 + gg * 4;

    const int e0 = eks[0], e1 = eks[1];
    const float* p0 = w2 + ((size_t)e0 * HH + s * 16) * OO + o;
    const float* p1 = w2 + ((size_t)e1 * HH + s * 16) * OO + o;
    const float* h0 = hs + s * 16;
    const float* h1 = hs + HH + s * 16;

    float4 a0 = {0,0,0,0}, a1 = {0,0,0,0}, c0 = {0,0,0,0}, c1 = {0,0,0,0};
    #pragma unroll
    for (int j = 0; j < 16; j += 2) {
        float4 w;
        w = *(const float4*)(p0 + (j + 0) * OO); FMA4(a0, h0[j + 0], w);
        w = *(const float4*)(p0 + (j + 1) * OO); FMA4(a1, h0[j + 1], w);
        w = *(const float4*)(p1 + (j + 0) * OO); FMA4(c0, h1[j + 0], w);
        w = *(const float4*)(p1 + (j + 1) * OO); FMA4(c1, h1[j + 1], w);
    }
    float4 t;
    t.x = (a0.x + a1.x) + (c0.x + c1.x);
    t.y = (a0.y + a1.y) + (c0.y + c1.y);
    t.z = (a0.z + a1.z) + (c0.z + c1.z);
    t.w = (a0.w + a1.w) + (c0.w + c1.w);

    // reduce across the 4 k-quarters (lanes 4g+s, same warp)
    #pragma unroll
    for (int off = 1; off <= 2; off <<= 1) {
        t.x += __shfl_xor_sync(0xFFFFFFFFu, t.x, off);
        t.y += __shfl_xor_sync(0xFFFFFFFFu, t.y, off);
        t.z += __shfl_xor_sync(0xFFFFFFFFu, t.z, off);
        t.w += __shfl_xor_sync(0xFFFFFFFFu, t.w, off);
    }

    if (g < 125 && s == 0) {
        const float gk0 = gks[0], gk1 = gks[1];
        float4 bb0 = *(const float4*)(b2 + (size_t)e0 * OO + o);
        float4 bb1 = *(const float4*)(b2 + (size_t)e1 * OO + o);
        float4 r;
        r.x = t.x + gk0 * bb0.x + gk1 * bb1.x;
        r.y = t.y + gk0 * bb0.y + gk1 * bb1.y;
        r.z = t.z + gk0 * bb0.z + gk1 * bb1.z;
        r.w = t.w + gk0 * bb0.w + gk1 * bb1.w;
        *(float4*)(out + rb * OO + o) = r;
    }
}

// Inputs: x, gate_w, gate_b, w1, b1, w2, b2. Output: f32 [32,1000]
extern "C" void kernel_launch(void* const* d_in, const int* in_sizes, int n_in,
                              void* d_out, int out_size) {
    const float* x  = (const float*)d_in[0];
    const float* gw = (const float*)d_in[1];
    const float* gb = (const float*)d_in[2];
    const float* w1 = (const float*)d_in[3];
    const float* b1 = (const float*)d_in[4];
    const float* w2 = (const float*)d_in[5];
    const float* b2 = (const float*)d_in[6];
    float* out = (float*)d_out;

    moe_fused<<<NBLK, NTHR>>>(x, gw, gb, w1, b1, w2, b2, out);
}

// round 5
// speedup vs baseline: 6.4742x; 1.1551x over previous
#include <cuda_runtime.h>
#include <math.h>

#define BB 32
#define DD 1024
#define HH 64
#define OO 1000
#define EE 6
#define NBLK 128
#define NTHR 256

// Scratch + grid barrier (monotonic counter, never reset: wrap-safe)
__device__ float        g_h[BB * 2 * HH];    // gate-pre-scaled hidden
__device__ float        g_gw2[BB * 2];
__device__ int          g_ge2[BB * 2];
__device__ unsigned int g_bar;               // zero-initialized

#define FMA4(acc, v, w) do { (acc).x += (v)*(w).x; (acc).y += (v)*(w).y; \
                             (acc).z += (v)*(w).z; (acc).w += (v)*(w).w; } while (0)

__global__ void __launch_bounds__(NTHR) moe_fused(const float* __restrict__ x,
                                                  const float* __restrict__ gw,
                                                  const float* __restrict__ gb,
                                                  const float* __restrict__ w1,
                                                  const float* __restrict__ b1,
                                                  const float* __restrict__ w2,
                                                  const float* __restrict__ b2,
                                                  float* __restrict__ out) {
    const int bid = blockIdx.x;
    const int tid = threadIdx.x;
    const int warp = tid >> 5, lane = tid & 31;

    // 16B alignment REQUIRED: accessed via float4
    __shared__ __align__(16) float xs[DD];          // 4 KB
    __shared__ __align__(16) float part[32][32];    // 4 KB
    __shared__ __align__(16) float hs[2 * HH];
    __shared__ float logit[EE];
    __shared__ float gks[2];
    __shared__ int   eks[2];

    // ========== PHASE 1: gate + fc1. block = (b, k, col-half) ================
    // bid: b = bid>>2, k = (bid>>1)&1, ch = bid&1 (32 cols each)
    const int b = bid >> 2, k = (bid >> 1) & 1, ch = bid & 1;

    if (tid < DD / 4)
        ((float4*)xs)[tid] = ((const float4*)(x + b * DD))[tid];
    __syncthreads();

    // gate logits: warp w -> expert w
    if (warp < EE) {
        float s = 0.0f;
        #pragma unroll 8
        for (int i = lane; i < DD; i += 32) s += xs[i] * gw[i * EE + warp];
        #pragma unroll
        for (int off = 16; off > 0; off >>= 1)
            s += __shfl_down_sync(0xFFFFFFFFu, s, off);
        if (lane == 0) logit[warp] = s + gb[warp];
    }
    __syncthreads();

    // top-2 + 2-way softmax (redundant per thread, cheap)
    float v[EE];
    #pragma unroll
    for (int e = 0; e < EE; ++e) v[e] = logit[e];
    int i1 = 0; float m1 = v[0];
    #pragma unroll
    for (int e = 1; e < EE; ++e) if (v[e] > m1) { m1 = v[e]; i1 = e; }
    int i2 = -1; float m2 = -INFINITY;
    #pragma unroll
    for (int e = 0; e < EE; ++e) if (e != i1 && v[e] > m2) { m2 = v[e]; i2 = e; }
    const float g1 = 1.0f / (1.0f + expf(m2 - m1));     // m1 >= m2: stable
    const float gk = (k == 0) ? g1 : (1.0f - g1);
    const int   e  = (k == 0) ? i1 : i2;
    if (tid == 0 && ch == 0) { g_gw2[b * 2 + k] = gk; g_ge2[b * 2 + k] = e; }

    // fc1 (32 cols of this half): dg = tid>>3 (32 d-groups of 32),
    // cg = tid&7 (4 cols each). 32 independent LDG.128 per thread.
    {
        const int dg = tid >> 3, cg = tid & 7;
        const float* wbase = w1 + ((size_t)e * DD + dg * 32) * HH + ch * 32 + cg * 4;
        const float* xp = xs + dg * 32;
        float4 a0 = {0,0,0,0}, a1 = {0,0,0,0}, a2 = {0,0,0,0}, a3 = {0,0,0,0};
        #pragma unroll
        for (int d = 0; d < 32; d += 4) {
            float4 w;
            w = *(const float4*)(wbase + (d + 0) * HH); FMA4(a0, xp[d + 0], w);
            w = *(const float4*)(wbase + (d + 1) * HH); FMA4(a1, xp[d + 1], w);
            w = *(const float4*)(wbase + (d + 2) * HH); FMA4(a2, xp[d + 2], w);
            w = *(const float4*)(wbase + (d + 3) * HH); FMA4(a3, xp[d + 3], w);
        }
        float4 t;
        t.x = (a0.x + a1.x) + (a2.x + a3.x);
        t.y = (a0.y + a1.y) + (a2.y + a3.y);
        t.z = (a0.z + a1.z) + (a2.z + a3.z);
        t.w = (a0.w + a1.w) + (a2.w + a3.w);
        *(float4*)&part[dg][cg * 4] = t;
    }
    __syncthreads();

    if (tid < 32) {
        float s = 0.0f;
        #pragma unroll
        for (int dg = 0; dg < 32; ++dg) s += part[dg][tid];
        const int col = ch * 32 + tid;
        s += b1[e * HH + col];
        g_h[(b * 2 + k) * HH + col] = gk * fmaxf(s, 0.0f);  // gate pre-applied
    }

    // ========== GRID BARRIER (128 blocks, all resident on 148 SMs) ===========
    __threadfence();              // publish g_h / g_gw2 / g_ge2
    __syncthreads();
    if (tid == 0) {
        unsigned old = atomicAdd(&g_bar, 1u);
        unsigned target = ((old >> 7) + 1u) << 7;       // next multiple of 128
        const volatile unsigned* p = &g_bar;
        while ((int)(*p - target) < 0) {}
    }
    __syncthreads();
    __threadfence();              // acquire before reading peers' writes

    // ========== PHASE 2: fc2 + combine. block = (row, O-chunk of 256) ========
    const int rb = bid >> 2, oc = bid & 3;
    const int olen = (oc < 3) ? 256 : 232;              // 3*256 + 232 = 1000
    const int obase = oc * 256;

    if (tid < 2 * HH) hs[tid] = g_h[rb * 2 * HH + tid];
    if (tid < 2) { gks[tid] = g_gw2[rb * 2 + tid]; eks[tid] = g_ge2[rb * 2 + tid]; }
    __syncthreads();

    const int g  = tid >> 2;                            // float4 group 0..63
    const int s  = tid & 3;                             // k-quarter (16 k each)
    const int ng = olen >> 2;                           // valid groups (64 or 58)
    const int gg = (g < ng) ? g : (ng - 1);             // clamp for safe loads
    const int o  = obase + gg * 4;

    const int e0 = eks[0], e1 = eks[1];
    const float* p0 = w2 + ((size_t)e0 * HH + s * 16) * OO + o;
    const float* p1 = w2 + ((size_t)e1 * HH + s * 16) * OO + o;
    const float* h0 = hs + s * 16;
    const float* h1 = hs + HH + s * 16;

    float4 a0 = {0,0,0,0}, a1 = {0,0,0,0}, c0 = {0,0,0,0}, c1 = {0,0,0,0};
    #pragma unroll
    for (int j = 0; j < 16; j += 2) {
        float4 w;
        w = *(const float4*)(p0 + (j + 0) * OO); FMA4(a0, h0[j + 0], w);
        w = *(const float4*)(p0 + (j + 1) * OO); FMA4(a1, h0[j + 1], w);
        w = *(const float4*)(p1 + (j + 0) * OO); FMA4(c0, h1[j + 0], w);
        w = *(const float4*)(p1 + (j + 1) * OO); FMA4(c1, h1[j + 1], w);
    }
    float4 t;
    t.x = (a0.x + a1.x) + (c0.x + c1.x);
    t.y = (a0.y + a1.y) + (c0.y + c1.y);
    t.z = (a0.z + a1.z) + (c0.z + c1.z);
    t.w = (a0.w + a1.w) + (c0.w + c1.w);

    // reduce across the 4 k-quarters (lanes 4g+s share a warp)
    #pragma unroll
    for (int off = 1; off <= 2; off <<= 1) {
        t.x += __shfl_xor_sync(0xFFFFFFFFu, t.x, off);
        t.y += __shfl_xor_sync(0xFFFFFFFFu, t.y, off);
        t.z += __shfl_xor_sync(0xFFFFFFFFu, t.z, off);
        t.w += __shfl_xor_sync(0xFFFFFFFFu, t.w, off);
    }

    if (g < ng && s == 0) {
        const float gk0 = gks[0], gk1 = gks[1];
        float4 bb0 = *(const float4*)(b2 + (size_t)e0 * OO + o);
        float4 bb1 = *(const float4*)(b2 + (size_t)e1 * OO + o);
        float4 r;
        r.x = t.x + gk0 * bb0.x + gk1 * bb1.x;
        r.y = t.y + gk0 * bb0.y + gk1 * bb1.y;
        r.z = t.z + gk0 * bb0.z + gk1 * bb1.z;
        r.w = t.w + gk0 * bb0.w + gk1 * bb1.w;
        *(float4*)(out + rb * OO + o) = r;
    }
}

// Inputs: x, gate_w, gate_b, w1, b1, w2, b2. Output: f32 [32,1000]
extern "C" void kernel_launch(void* const* d_in, const int* in_sizes, int n_in,
                              void* d_out, int out_size) {
    const float* x  = (const float*)d_in[0];
    const float* gw = (const float*)d_in[1];
    const float* gb = (const float*)d_in[2];
    const float* w1 = (const float*)d_in[3];
    const float* b1 = (const float*)d_in[4];
    const float* w2 = (const float*)d_in[5];
    const float* b2 = (const float*)d_in[6];
    float* out = (float*)d_out;

    moe_fused<<<NBLK, NTHR>>>(x, gw, gb, w1, b1, w2, b2, out);
}

// round 7
// speedup vs baseline: 7.1136x; 1.0988x over previous
#include <cuda_runtime.h>
#include <math.h>

#define BB 32
#define DD 1024
#define HH 64
#define OO 1000
#define EE 6
#define NBLK 128
#define NTHR 256

// Scratch + grid barrier (monotonic counter, never reset: wrap-safe)
__device__ __align__(16) float g_h[BB * 2 * HH];   // gate-pre-scaled hidden
__device__ unsigned int g_bar;                     // zero-initialized

__device__ __forceinline__ void fma4(float4& acc, float v, const float4& w) {
    acc.x += v * w.x; acc.y += v * w.y; acc.z += v * w.z; acc.w += v * w.w;
}

__global__ void __launch_bounds__(NTHR) moe_fused(const float* __restrict__ x,
                                                  const float* __restrict__ gw,
                                                  const float* __restrict__ gb,
                                                  const float* __restrict__ w1,
                                                  const float* __restrict__ b1,
                                                  const float* __restrict__ w2,
                                                  const float* __restrict__ b2,
                                                  float* __restrict__ out) {
    const int bid = blockIdx.x;
    const int tid = threadIdx.x;
    const int warp = tid >> 5, lane = tid & 31;

    __shared__ __align__(16) float xs[DD];          // 4 KB
    __shared__ __align__(16) float part[32][32];    // 4 KB
    __shared__ float logit[EE];

    // Block roles: phase 1 (b, k, col-half) and phase 2 (same b, O-chunk oc)
    const int b = bid >> 2, k = (bid >> 1) & 1, ch = bid & 1;
    const int oc = bid & 3;

    // ---- stage x to smem (1 float4/thread) + gate logits from GLOBAL x -----
    ((float4*)xs)[tid] = ((const float4*)(x + b * DD))[tid];
    if (warp < EE) {
        const float* xr = x + b * DD;
        float s = 0.0f;
        #pragma unroll 8
        for (int i = lane; i < DD; i += 32) s += xr[i] * gw[i * EE + warp];
        #pragma unroll
        for (int off = 16; off > 0; off >>= 1)
            s += __shfl_down_sync(0xFFFFFFFFu, s, off);
        if (lane == 0) logit[warp] = s + gb[warp];
    }
    __syncthreads();

    // ---- top-2 + 2-way softmax (every thread; kept in registers) ----------
    float v[EE];
    #pragma unroll
    for (int e = 0; e < EE; ++e) v[e] = logit[e];
    int i1 = 0; float m1 = v[0];
    #pragma unroll
    for (int e = 1; e < EE; ++e) if (v[e] > m1) { m1 = v[e]; i1 = e; }
    int i2 = -1; float m2 = -INFINITY;
    #pragma unroll
    for (int e = 0; e < EE; ++e) if (e != i1 && v[e] > m2) { m2 = v[e]; i2 = e; }
    const float g1  = 1.0f / (1.0f + expf(m2 - m1));   // m1 >= m2: stable
    const float gk  = (k == 0) ? g1 : (1.0f - g1);
    const int   e   = (k == 0) ? i1 : i2;
    const int   e0  = i1, e1 = i2;
    const float gk0 = g1, gk1 = 1.0f - g1;

    // ---- fc1 (32 cols of half ch): dg=tid>>3 (32 d-groups), cg=tid&7 -------
    float4 t;
    {
        const int dg = tid >> 3, cg = tid & 7;
        const float* wbase = w1 + ((size_t)e * DD + dg * 32) * HH + ch * 32 + cg * 4;
        const float* xp = xs + dg * 32;
        float4 a0 = {0,0,0,0}, a1 = {0,0,0,0}, a2 = {0,0,0,0}, a3 = {0,0,0,0};
        #pragma unroll
        for (int d = 0; d < 32; d += 4) {
            fma4(a0, xp[d + 0], *(const float4*)(wbase + (d + 0) * HH));
            fma4(a1, xp[d + 1], *(const float4*)(wbase + (d + 1) * HH));
            fma4(a2, xp[d + 2], *(const float4*)(wbase + (d + 2) * HH));
            fma4(a3, xp[d + 3], *(const float4*)(wbase + (d + 3) * HH));
        }
        t.x = (a0.x + a1.x) + (a2.x + a3.x);
        t.y = (a0.y + a1.y) + (a2.y + a3.y);
        t.z = (a0.z + a1.z) + (a2.z + a3.z);
        t.w = (a0.w + a1.w) + (a2.w + a3.w);
    }

    // ---- PRE-BARRIER PREFETCH of all phase-2 w2/b2 data into registers -----
    // (addresses depend only on e0/e1/tid; loads fly during reduce + barrier)
    const int g  = tid >> 2;                 // float4 group within O-chunk
    const int s  = tid & 3;                  // k-quarter (16 k each)
    const int olen = (oc < 3) ? 256 : 232;
    const int ng = olen >> 2;
    const int gg = (g < ng) ? g : (ng - 1);  // clamp for safe loads
    const int o  = oc * 256 + gg * 4;

    float4 w2r0[16], w2r1[16];
    const float* p0 = w2 + ((size_t)e0 * HH + s * 16) * OO + o;
    const float* p1 = w2 + ((size_t)e1 * HH + s * 16) * OO + o;
    #pragma unroll
    for (int j = 0; j < 16; ++j) w2r0[j] = __ldg((const float4*)(p0 + j * OO));
    #pragma unroll
    for (int j = 0; j < 16; ++j) w2r1[j] = __ldg((const float4*)(p1 + j * OO));
    const float4 bb0 = __ldg((const float4*)(b2 + (size_t)e0 * OO + o));
    const float4 bb1 = __ldg((const float4*)(b2 + (size_t)e1 * OO + o));

    // ---- finish fc1: cross-d reduce in smem, write gate-scaled h -----------
    {
        const int dg = tid >> 3, cg = tid & 7;
        *(float4*)&part[dg][cg * 4] = t;
    }
    __syncthreads();
    if (tid < 32) {
        float sum = 0.0f;
        #pragma unroll
        for (int dg = 0; dg < 32; ++dg) sum += part[dg][tid];
        const int col = ch * 32 + tid;
        sum += b1[e * HH + col];
        g_h[(b * 2 + k) * HH + col] = gk * fmaxf(sum, 0.0f);
    }

    // ---- GRID BARRIER (128 blocks, all resident) ---------------------------
    __threadfence();
    __syncthreads();
    if (tid == 0) {
        unsigned old = atomicAdd(&g_bar, 1u);
        unsigned target = ((old >> 7) + 1u) << 7;     // next multiple of 128
        const volatile unsigned* p = &g_bar;
        while ((int)(*p - target) < 0) {}
    }
    __syncthreads();
    __threadfence();

    // ---- PHASE 2: load h (direct, contiguous) and consume prefetched w2 ----
    float4 acc = {0, 0, 0, 0};
    {
        const float4* h0p = (const float4*)(g_h + (b * 2 + 0) * HH + s * 16);
        const float4* h1p = (const float4*)(g_h + (b * 2 + 1) * HH + s * 16);
        #pragma unroll
        for (int q = 0; q < 4; ++q) {
            float4 hq = h0p[q];
            fma4(acc, hq.x, w2r0[q * 4 + 0]);
            fma4(acc, hq.y, w2r0[q * 4 + 1]);
            fma4(acc, hq.z, w2r0[q * 4 + 2]);
            fma4(acc, hq.w, w2r0[q * 4 + 3]);
        }
        #pragma unroll
        for (int q = 0; q < 4; ++q) {
            float4 hq = h1p[q];
            fma4(acc, hq.x, w2r1[q * 4 + 0]);
            fma4(acc, hq.y, w2r1[q * 4 + 1]);
            fma4(acc, hq.z, w2r1[q * 4 + 2]);
            fma4(acc, hq.w, w2r1[q * 4 + 3]);
        }
    }

    // reduce across the 4 k-quarters (lanes 4g+s share a warp)
    #pragma unroll
    for (int off = 1; off <= 2; off <<= 1) {
        acc.x += __shfl_xor_sync(0xFFFFFFFFu, acc.x, off);
        acc.y += __shfl_xor_sync(0xFFFFFFFFu, acc.y, off);
        acc.z += __shfl_xor_sync(0xFFFFFFFFu, acc.z, off);
        acc.w += __shfl_xor_sync(0xFFFFFFFFu, acc.w, off);
    }

    if (g < ng && s == 0) {
        float4 r;
        r.x = acc.x + gk0 * bb0.x + gk1 * bb1.x;
        r.y = acc.y + gk0 * bb0.y + gk1 * bb1.y;
        r.z = acc.z + gk0 * bb0.z + gk1 * bb1.z;
        r.w = acc.w + gk0 * bb0.w + gk1 * bb1.w;
        *(float4*)(out + b * OO + o) = r;
    }
}

// Inputs: x, gate_w, gate_b, w1, b1, w2, b2. Output: f32 [32,1000]
extern "C" void kernel_launch(void* const* d_in, const int* in_sizes, int n_in,
                              void* d_out, int out_size) {
    const float* x  = (const float*)d_in[0];
    const float* gw = (const float*)d_in[1];
    const float* gb = (const float*)d_in[2];
    const float* w1 = (const float*)d_in[3];
    const float* b1 = (const float*)d_in[4];
    const float* w2 = (const float*)d_in[5];
    const float* b2 = (const float*)d_in[6];
    float* out = (float*)d_out;

    moe_fused<<<NBLK, NTHR>>>(x, gw, gb, w1, b1, w2, b2, out);
}

// round 8
// speedup vs baseline: 7.4062x; 1.0411x over previous
#include <cuda_runtime.h>
#include <math.h>

#define BB 32
#define DD 1024
#define HH 64
#define OO 1000
#define EE 6
#define NBLK 128
#define NTHR 256

// Scratch + per-row group barriers (monotonic counters, never reset: wrap-safe)
__device__ __align__(16) float g_h[BB * 2 * HH];   // gate-pre-scaled hidden
struct __align__(128) PadCnt { unsigned int c; unsigned int pad[31]; };
__device__ PadCnt g_grp[BB];                       // zero-initialized

__device__ __forceinline__ void fma4(float4& acc, float v, const float4& w) {
    acc.x += v * w.x; acc.y += v * w.y; acc.z += v * w.z; acc.w += v * w.w;
}

__global__ void __launch_bounds__(NTHR) moe_fused(const float* __restrict__ x,
                                                  const float* __restrict__ gw,
                                                  const float* __restrict__ gb,
                                                  const float* __restrict__ w1,
                                                  const float* __restrict__ b1,
                                                  const float* __restrict__ w2,
                                                  const float* __restrict__ b2,
                                                  float* __restrict__ out) {
    const int bid = blockIdx.x;
    const int tid = threadIdx.x;
    const int warp = tid >> 5, lane = tid & 31;

    __shared__ __align__(16) float xs[DD];          // 4 KB
    __shared__ __align__(16) float part[32][32];    // 4 KB
    __shared__ float logit[EE];

    // Block roles: phase 1 (b, k, col-half) and phase 2 (same b, O-chunk oc)
    const int b = bid >> 2, k = (bid >> 1) & 1, ch = bid & 1;
    const int oc = bid & 3;

    // ---- stage x to smem (1 float4/thread) + gate logits from GLOBAL x -----
    ((float4*)xs)[tid] = ((const float4*)(x + b * DD))[tid];
    if (warp < EE) {
        const float* xr = x + b * DD;
        float s = 0.0f;
        #pragma unroll 8
        for (int i = lane; i < DD; i += 32) s += xr[i] * gw[i * EE + warp];
        #pragma unroll
        for (int off = 16; off > 0; off >>= 1)
            s += __shfl_down_sync(0xFFFFFFFFu, s, off);
        if (lane == 0) logit[warp] = s + gb[warp];
    }
    __syncthreads();

    // ---- top-2 + 2-way softmax (every thread; kept in registers) ----------
    float v[EE];
    #pragma unroll
    for (int e = 0; e < EE; ++e) v[e] = logit[e];
    int i1 = 0; float m1 = v[0];
    #pragma unroll
    for (int e = 1; e < EE; ++e) if (v[e] > m1) { m1 = v[e]; i1 = e; }
    int i2 = -1; float m2 = -INFINITY;
    #pragma unroll
    for (int e = 0; e < EE; ++e) if (e != i1 && v[e] > m2) { m2 = v[e]; i2 = e; }
    const float g1  = 1.0f / (1.0f + expf(m2 - m1));   // m1 >= m2: stable
    const float gk  = (k == 0) ? g1 : (1.0f - g1);
    const int   e   = (k == 0) ? i1 : i2;
    const int   e0  = i1, e1 = i2;
    const float gk0 = g1, gk1 = 1.0f - g1;

    // ---- fc1 (32 cols of half ch): dg=tid>>3 (32 d-groups), cg=tid&7 -------
    float4 t;
    {
        const int dg = tid >> 3, cg = tid & 7;
        const float* wbase = w1 + ((size_t)e * DD + dg * 32) * HH + ch * 32 + cg * 4;
        const float* xp = xs + dg * 32;
        float4 a0 = {0,0,0,0}, a1 = {0,0,0,0}, a2 = {0,0,0,0}, a3 = {0,0,0,0};
        #pragma unroll
        for (int d = 0; d < 32; d += 4) {
            fma4(a0, xp[d + 0], *(const float4*)(wbase + (d + 0) * HH));
            fma4(a1, xp[d + 1], *(const float4*)(wbase + (d + 1) * HH));
            fma4(a2, xp[d + 2], *(const float4*)(wbase + (d + 2) * HH));
            fma4(a3, xp[d + 3], *(const float4*)(wbase + (d + 3) * HH));
        }
        t.x = (a0.x + a1.x) + (a2.x + a3.x);
        t.y = (a0.y + a1.y) + (a2.y + a3.y);
        t.z = (a0.z + a1.z) + (a2.z + a3.z);
        t.w = (a0.w + a1.w) + (a2.w + a3.w);
    }

    // ---- PRE-BARRIER PREFETCH of all phase-2 w2/b2 data into registers -----
    const int g  = tid >> 2;                 // float4 group within O-chunk
    const int s  = tid & 3;                  // k-quarter (16 k each)
    const int olen = (oc < 3) ? 256 : 232;
    const int ng = olen >> 2;
    const int gg = (g < ng) ? g : (ng - 1);  // clamp for safe loads
    const int o  = oc * 256 + gg * 4;

    float4 w2r0[16], w2r1[16];
    const float* p0 = w2 + ((size_t)e0 * HH + s * 16) * OO + o;
    const float* p1 = w2 + ((size_t)e1 * HH + s * 16) * OO + o;
    #pragma unroll
    for (int j = 0; j < 16; ++j) w2r0[j] = __ldg((const float4*)(p0 + j * OO));
    #pragma unroll
    for (int j = 0; j < 16; ++j) w2r1[j] = __ldg((const float4*)(p1 + j * OO));
    const float4 bb0 = __ldg((const float4*)(b2 + (size_t)e0 * OO + o));
    const float4 bb1 = __ldg((const float4*)(b2 + (size_t)e1 * OO + o));

    // ---- finish fc1: cross-d reduce in smem, write gate-scaled h -----------
    {
        const int dg = tid >> 3, cg = tid & 7;
        *(float4*)&part[dg][cg * 4] = t;
    }
    __syncthreads();
    if (tid < 32) {
        float sum = 0.0f;
        #pragma unroll
        for (int dg = 0; dg < 32; ++dg) sum += part[dg][tid];
        const int col = ch * 32 + tid;
        sum += b1[e * HH + col];
        g_h[(b * 2 + k) * HH + col] = gk * fmaxf(sum, 0.0f);
    }

    // ---- GROUP BARRIER: only the 4 blocks of row b (bids 4b..4b+3) ---------
    __threadfence();              // publish this block's g_h writes
    __syncthreads();
    if (tid == 0) {
        unsigned old = atomicAdd(&g_grp[b].c, 1u);
        unsigned target = ((old >> 2) + 1u) << 2;     // next multiple of 4
        const volatile unsigned* p = &g_grp[b].c;
        while ((int)(*p - target) < 0) {}
    }
    __syncthreads();
    __threadfence();              // acquire before reading siblings' h

    // ---- PHASE 2: load h (direct, contiguous) and consume prefetched w2 ----
    float4 acc = {0, 0, 0, 0};
    {
        const float4* h0p = (const float4*)(g_h + (b * 2 + 0) * HH + s * 16);
        const float4* h1p = (const float4*)(g_h + (b * 2 + 1) * HH + s * 16);
        #pragma unroll
        for (int q = 0; q < 4; ++q) {
            float4 hq = h0p[q];
            fma4(acc, hq.x, w2r0[q * 4 + 0]);
            fma4(acc, hq.y, w2r0[q * 4 + 1]);
            fma4(acc, hq.z, w2r0[q * 4 + 2]);
            fma4(acc, hq.w, w2r0[q * 4 + 3]);
        }
        #pragma unroll
        for (int q = 0; q < 4; ++q) {
            float4 hq = h1p[q];
            fma4(acc, hq.x, w2r1[q * 4 + 0]);
            fma4(acc, hq.y, w2r1[q * 4 + 1]);
            fma4(acc, hq.z, w2r1[q * 4 + 2]);
            fma4(acc, hq.w, w2r1[q * 4 + 3]);
        }
    }

    // reduce across the 4 k-quarters (lanes 4g+s share a warp)
    #pragma unroll
    for (int off = 1; off <= 2; off <<= 1) {
        acc.x += __shfl_xor_sync(0xFFFFFFFFu, acc.x, off);
        acc.y += __shfl_xor_sync(0xFFFFFFFFu, acc.y, off);
        acc.z += __shfl_xor_sync(0xFFFFFFFFu, acc.z, off);
        acc.w += __shfl_xor_sync(0xFFFFFFFFu, acc.w, off);
    }

    if (g < ng && s == 0) {
        float4 r;
        r.x = acc.x + gk0 * bb0.x + gk1 * bb1.x;
        r.y = acc.y + gk0 * bb0.y + gk1 * bb1.y;
        r.z = acc.z + gk0 * bb0.z + gk1 * bb1.z;
        r.w = acc.w + gk0 * bb0.w + gk1 * bb1.w;
        *(float4*)(out + b * OO + o) = r;
    }
}

// Inputs: x, gate_w, gate_b, w1, b1, w2, b2. Output: f32 [32,1000]
extern "C" void kernel_launch(void* const* d_in, const int* in_sizes, int n_in,
                              void* d_out, int out_size) {
    const float* x  = (const float*)d_in[0];
    const float* gw = (const float*)d_in[1];
    const float* gb = (const float*)d_in[2];
    const float* w1 = (const float*)d_in[3];
    const float* b1 = (const float*)d_in[4];
    const float* w2 = (const float*)d_in[5];
    const float* b2 = (const float*)d_in[6];
    float* out = (float*)d_out;

    moe_fused<<<NBLK, NTHR>>>(x, gw, gb, w1, b1, w2, b2, out);
}

// round 9
// speedup vs baseline: 7.4637x; 1.0078x over previous
#include <cuda_runtime.h>
#include <math.h>

#define BB 32
#define DD 1024
#define HH 64
#define OO 1000
#define EE 6
#define NBLK 128
#define NTHR 256

// Scratch + per-row group barriers (monotonic counters, never reset: wrap-safe)
__device__ __align__(16) float g_h[BB * 2 * HH];   // gate-pre-scaled hidden
struct __align__(128) PadCnt { unsigned int c; unsigned int pad[31]; };
__device__ PadCnt g_grp[BB];                       // zero-initialized

__device__ __forceinline__ void fma4(float4& acc, float v, const float4& w) {
    acc.x += v * w.x; acc.y += v * w.y; acc.z += v * w.z; acc.w += v * w.w;
}

__global__ void __launch_bounds__(NTHR) moe_fused(const float* __restrict__ x,
                                                  const float* __restrict__ gw,
                                                  const float* __restrict__ gb,
                                                  const float* __restrict__ w1,
                                                  const float* __restrict__ b1,
                                                  const float* __restrict__ w2,
                                                  const float* __restrict__ b2,
                                                  float* __restrict__ out) {
    const int bid = blockIdx.x;
    const int tid = threadIdx.x;
    const int warp = tid >> 5, lane = tid & 31;

    __shared__ __align__(16) float xs[DD];          // 4 KB
    __shared__ __align__(16) float part[8][32];     // 1 KB
    __shared__ float logit[EE];

    // Block roles: phase 1 (b, k, col-half) and phase 2 (same b, O-chunk oc)
    const int b = bid >> 2, k = (bid >> 1) & 1, ch = bid & 1;
    const int oc = bid & 3;

    // ---- stage x to smem (1 float4/thread) + gate logits from GLOBAL x -----
    ((float4*)xs)[tid] = ((const float4*)(x + b * DD))[tid];
    if (warp < EE) {
        const float* xr = x + b * DD;
        float s0 = 0.f, s1 = 0.f, s2 = 0.f, s3 = 0.f;
        #pragma unroll
        for (int i = 0; i < DD / 128; ++i) {        // 4-way chain split
            int d = lane + 128 * i;
            s0 += xr[d]      * gw[(d)      * EE + warp];
            s1 += xr[d + 32] * gw[(d + 32) * EE + warp];
            s2 += xr[d + 64] * gw[(d + 64) * EE + warp];
            s3 += xr[d + 96] * gw[(d + 96) * EE + warp];
        }
        float s = (s0 + s1) + (s2 + s3);
        #pragma unroll
        for (int off = 16; off > 0; off >>= 1)
            s += __shfl_down_sync(0xFFFFFFFFu, s, off);
        if (lane == 0) logit[warp] = s + gb[warp];
    }
    __syncthreads();

    // ---- top-2 + 2-way softmax (every thread; kept in registers) ----------
    float v[EE];
    #pragma unroll
    for (int e = 0; e < EE; ++e) v[e] = logit[e];
    int i1 = 0; float m1 = v[0];
    #pragma unroll
    for (int e = 1; e < EE; ++e) if (v[e] > m1) { m1 = v[e]; i1 = e; }
    int i2 = -1; float m2 = -INFINITY;
    #pragma unroll
    for (int e = 0; e < EE; ++e) if (e != i1 && v[e] > m2) { m2 = v[e]; i2 = e; }
    const float g1  = 1.0f / (1.0f + __expf(m2 - m1));  // m1 >= m2: stable
    const float gk  = (k == 0) ? g1 : (1.0f - g1);
    const int   e   = (k == 0) ? i1 : i2;
    const int   e0  = i1, e1 = i2;
    const float gk0 = g1, gk1 = 1.0f - g1;

    // Prefetch fc1 bias early (consumed after the reduce)
    const float biasv = __ldg(&b1[e * HH + ch * 32 + (tid & 31)]);

    // ---- fc1 (32 cols of half ch): dg=tid>>3 (32 d-groups), cg=tid&7 -------
    float4 t;
    const int dg = tid >> 3, cg = tid & 7;
    {
        const float* wbase = w1 + ((size_t)e * DD + dg * 32) * HH + ch * 32 + cg * 4;
        const float* xp = xs + dg * 32;
        float4 a0 = {0,0,0,0}, a1 = {0,0,0,0}, a2 = {0,0,0,0}, a3 = {0,0,0,0};
        #pragma unroll
        for (int d = 0; d < 32; d += 4) {
            fma4(a0, xp[d + 0], *(const float4*)(wbase + (d + 0) * HH));
            fma4(a1, xp[d + 1], *(const float4*)(wbase + (d + 1) * HH));
            fma4(a2, xp[d + 2], *(const float4*)(wbase + (d + 2) * HH));
            fma4(a3, xp[d + 3], *(const float4*)(wbase + (d + 3) * HH));
        }
        t.x = (a0.x + a1.x) + (a2.x + a3.x);
        t.y = (a0.y + a1.y) + (a2.y + a3.y);
        t.z = (a0.z + a1.z) + (a2.z + a3.z);
        t.w = (a0.w + a1.w) + (a2.w + a3.w);
    }

    // ---- PRE-BARRIER PREFETCH of all phase-2 w2/b2 data into registers -----
    const int g  = tid >> 2;                 // float4 group within O-chunk
    const int s  = tid & 3;                  // k-quarter (16 k each)
    const int olen = (oc < 3) ? 256 : 232;
    const int ng = olen >> 2;
    const int gg = (g < ng) ? g : (ng - 1);  // clamp for safe loads
    const int o  = oc * 256 + gg * 4;

    float4 w2r0[16], w2r1[16];
    const float* p0 = w2 + ((size_t)e0 * HH + s * 16) * OO + o;
    const float* p1 = w2 + ((size_t)e1 * HH + s * 16) * OO + o;
    #pragma unroll
    for (int j = 0; j < 16; ++j) w2r0[j] = __ldg((const float4*)(p0 + j * OO));
    #pragma unroll
    for (int j = 0; j < 16; ++j) w2r1[j] = __ldg((const float4*)(p1 + j * OO));
    const float4 bb0 = __ldg((const float4*)(b2 + (size_t)e0 * OO + o));
    const float4 bb1 = __ldg((const float4*)(b2 + (size_t)e1 * OO + o));

    // ---- finish fc1: fold 4 d-groups in-warp via shfl, then 8-deep smem ----
    // warp holds dg = 4*warp .. 4*warp+3 (lane = (dg&3)*8 + cg)
    #pragma unroll
    for (int off = 16; off >= 8; off >>= 1) {
        t.x += __shfl_xor_sync(0xFFFFFFFFu, t.x, off);
        t.y += __shfl_xor_sync(0xFFFFFFFFu, t.y, off);
        t.z += __shfl_xor_sync(0xFFFFFFFFu, t.z, off);
        t.w += __shfl_xor_sync(0xFFFFFFFFu, t.w, off);
    }
    if (lane < 8) *(float4*)&part[warp][lane * 4] = t;
    __syncthreads();
    if (tid < 32) {
        float sum = biasv;
        #pragma unroll
        for (int w = 0; w < 8; ++w) sum += part[w][tid];
        const int col = ch * 32 + tid;
        g_h[(b * 2 + k) * HH + col] = gk * fmaxf(sum, 0.0f);
    }

    // ---- GROUP BARRIER: only the 4 blocks of row b (bids 4b..4b+3) ---------
    // bar.sync orders block-mates' g_h stores to tid 0; atom.release publishes
    // them; consumer's ld.acquire + bar.sync completes the chain.
    __syncthreads();
    if (tid == 0) {
        unsigned int* cp = &g_grp[b].c;
        unsigned old;
        asm volatile("atom.add.release.gpu.global.u32 %0, [%1], 1;"
                     : "=r"(old) : "l"(cp) : "memory");
        unsigned target = ((old >> 2) + 1u) << 2;   // next multiple of 4
        unsigned cur;
        do {
            asm volatile("ld.acquire.gpu.global.u32 %0, [%1];"
                         : "=r"(cur) : "l"(cp) : "memory");
        } while ((int)(cur - target) < 0);
    }
    __syncthreads();

    // ---- PHASE 2: load h (direct, contiguous) and consume prefetched w2 ----
    float4 acc = {0, 0, 0, 0};
    {
        const float4* h0p = (const float4*)(g_h + (b * 2 + 0) * HH + s * 16);
        const float4* h1p = (const float4*)(g_h + (b * 2 + 1) * HH + s * 16);
        #pragma unroll
        for (int q = 0; q < 4; ++q) {
            float4 hq = h0p[q];
            fma4(acc, hq.x, w2r0[q * 4 + 0]);
            fma4(acc, hq.y, w2r0[q * 4 + 1]);
            fma4(acc, hq.z, w2r0[q * 4 + 2]);
            fma4(acc, hq.w, w2r0[q * 4 + 3]);
        }
        #pragma unroll
        for (int q = 0; q < 4; ++q) {
            float4 hq = h1p[q];
            fma4(acc, hq.x, w2r1[q * 4 + 0]);
            fma4(acc, hq.y, w2r1[q * 4 + 1]);
            fma4(acc, hq.z, w2r1[q * 4 + 2]);
            fma4(acc, hq.w, w2r1[q * 4 + 3]);
        }
    }

    // reduce across the 4 k-quarters (lanes 4g+s share a warp)
    #pragma unroll
    for (int off = 1; off <= 2; off <<= 1) {
        acc.x += __shfl_xor_sync(0xFFFFFFFFu, acc.x, off);
        acc.y += __shfl_xor_sync(0xFFFFFFFFu, acc.y, off);
        acc.z += __shfl_xor_sync(0xFFFFFFFFu, acc.z, off);
        acc.w += __shfl_xor_sync(0xFFFFFFFFu, acc.w, off);
    }

    if (g < ng && s == 0) {
        float4 r;
        r.x = acc.x + gk0 * bb0.x + gk1 * bb1.x;
        r.y = acc.y + gk0 * bb0.y + gk1 * bb1.y;
        r.z = acc.z + gk0 * bb0.z + gk1 * bb1.z;
        r.w = acc.w + gk0 * bb0.w + gk1 * bb1.w;
        *(float4*)(out + b * OO + o) = r;
    }
}

// Inputs: x, gate_w, gate_b, w1, b1, w2, b2. Output: f32 [32,1000]
extern "C" void kernel_launch(void* const* d_in, const int* in_sizes, int n_in,
                              void* d_out, int out_size) {
    const float* x  = (const float*)d_in[0];
    const float* gw = (const float*)d_in[1];
    const float* gb = (const float*)d_in[2];
    const float* w1 = (const float*)d_in[3];
    const float* b1 = (const float*)d_in[4];
    const float* w2 = (const float*)d_in[5];
    const float* b2 = (const float*)d_in[6];
    float* out = (float*)d_out;

    moe_fused<<<NBLK, NTHR>>>(x, gw, gb, w1, b1, w2, b2, out);
}

// round 11
// speedup vs baseline: 8.9195x; 1.1950x over previous
#include <cuda_runtime.h>
#include <cstdint>
#include <math.h>

#define BB 32
#define DD 1024
#define HH 64
#define OO 1000
#define EE 6
#define NBLK 128
#define NTHR 256
#define CLUSTER 4

__device__ __forceinline__ void fma4(float4& acc, float v, const float4& w) {
    acc.x += v * w.x; acc.y += v * w.y; acc.z += v * w.z; acc.w += v * w.w;
}

__device__ __forceinline__ unsigned int smem_u32(const void* p) {
    unsigned int a;
    asm("{ .reg .u64 t; cvta.to.shared.u64 t, %1; cvt.u32.u64 %0, t; }"
        : "=r"(a) : "l"(p));
    return a;
}

// Store one float into the same smem offset of cluster CTA `rank`.
__device__ __forceinline__ void dsmem_store(unsigned int local_addr, int rank, float v) {
    unsigned int rem;
    asm volatile("mapa.shared::cluster.u32 %0, %1, %2;"
                 : "=r"(rem) : "r"(local_addr), "r"(rank));
    asm volatile("st.shared::cluster.f32 [%0], %1;"
                 :: "r"(rem), "f"(v) : "memory");
}

__global__ void __launch_bounds__(NTHR) __cluster_dims__(CLUSTER, 1, 1)
moe_fused(const float* __restrict__ x,
          const float* __restrict__ gw,
          const float* __restrict__ gb,
          const float* __restrict__ w1,
          const float* __restrict__ b1,
          const float* __restrict__ w2,
          const float* __restrict__ b2,
          float* __restrict__ out) {
    const int bid = blockIdx.x;
    const int tid = threadIdx.x;
    const int warp = tid >> 5, lane = tid & 31;

    __shared__ __align__(16) float xs[DD];          // 4 KB
    __shared__ __align__(16) float part[8][32];     // 1 KB
    __shared__ __align__(16) float hs[2 * HH];      // row b's full h (both slots)
    __shared__ float logit[EE];

    // Cluster = the 4 blocks of row b. Phase-1 role (k, ch), phase-2 role oc.
    const int b = bid >> 2, k = (bid >> 1) & 1, ch = bid & 1;
    const int oc = bid & 3;

    // ---- stage x to smem (1 float4/thread) + gate logits from GLOBAL x -----
    ((float4*)xs)[tid] = ((const float4*)(x + b * DD))[tid];
    if (warp < EE) {
        const float* xr = x + b * DD;
        float s0 = 0.f, s1 = 0.f, s2 = 0.f, s3 = 0.f;
        #pragma unroll
        for (int i = 0; i < DD / 128; ++i) {        // 4-way chain split
            int d = lane + 128 * i;
            s0 += xr[d]      * gw[(d)      * EE + warp];
            s1 += xr[d + 32] * gw[(d + 32) * EE + warp];
            s2 += xr[d + 64] * gw[(d + 64) * EE + warp];
            s3 += xr[d + 96] * gw[(d + 96) * EE + warp];
        }
        float s = (s0 + s1) + (s2 + s3);
        #pragma unroll
        for (int off = 16; off > 0; off >>= 1)
            s += __shfl_down_sync(0xFFFFFFFFu, s, off);
        if (lane == 0) logit[warp] = s + gb[warp];
    }
    __syncthreads();

    // ---- top-2 + 2-way softmax (every thread; kept in registers) ----------
    float v[EE];
    #pragma unroll
    for (int e = 0; e < EE; ++e) v[e] = logit[e];
    int i1 = 0; float m1 = v[0];
    #pragma unroll
    for (int e = 1; e < EE; ++e) if (v[e] > m1) { m1 = v[e]; i1 = e; }
    int i2 = -1; float m2 = -INFINITY;
    #pragma unroll
    for (int e = 0; e < EE; ++e) if (e != i1 && v[e] > m2) { m2 = v[e]; i2 = e; }
    const float g1  = 1.0f / (1.0f + __expf(m2 - m1));  // m1 >= m2: stable
    const float gk  = (k == 0) ? g1 : (1.0f - g1);
    const int   e   = (k == 0) ? i1 : i2;
    const int   e0  = i1, e1 = i2;
    const float gk0 = g1, gk1 = 1.0f - g1;

    // Prefetch fc1 bias early (consumed after the reduce)
    const float biasv = __ldg(&b1[e * HH + ch * 32 + (tid & 31)]);

    // ---- fc1 (32 cols of half ch): dg=tid>>3 (32 d-groups), cg=tid&7 -------
    float4 t;
    {
        const int dg = tid >> 3, cg = tid & 7;
        const float* wbase = w1 + ((size_t)e * DD + dg * 32) * HH + ch * 32 + cg * 4;
        const float* xp = xs + dg * 32;
        float4 a0 = {0,0,0,0}, a1 = {0,0,0,0}, a2 = {0,0,0,0}, a3 = {0,0,0,0};
        #pragma unroll
        for (int d = 0; d < 32; d += 4) {
            fma4(a0, xp[d + 0], *(const float4*)(wbase + (d + 0) * HH));
            fma4(a1, xp[d + 1], *(const float4*)(wbase + (d + 1) * HH));
            fma4(a2, xp[d + 2], *(const float4*)(wbase + (d + 2) * HH));
            fma4(a3, xp[d + 3], *(const float4*)(wbase + (d + 3) * HH));
        }
        t.x = (a0.x + a1.x) + (a2.x + a3.x);
        t.y = (a0.y + a1.y) + (a2.y + a3.y);
        t.z = (a0.z + a1.z) + (a2.z + a3.z);
        t.w = (a0.w + a1.w) + (a2.w + a3.w);
    }

    // ---- PRE-BARRIER PREFETCH of all phase-2 w2/b2 data into registers -----
    const int g  = tid >> 2;                 // float4 group within O-chunk
    const int s  = tid & 3;                  // k-quarter (16 k each)
    const int olen = (oc < 3) ? 256 : 232;
    const int ng = olen >> 2;
    const int gg = (g < ng) ? g : (ng - 1);  // clamp for safe loads
    const int o  = oc * 256 + gg * 4;

    float4 w2r0[16], w2r1[16];
    const float* p0 = w2 + ((size_t)e0 * HH + s * 16) * OO + o;
    const float* p1 = w2 + ((size_t)e1 * HH + s * 16) * OO + o;
    #pragma unroll
    for (int j = 0; j < 16; ++j) w2r0[j] = __ldg((const float4*)(p0 + j * OO));
    #pragma unroll
    for (int j = 0; j < 16; ++j) w2r1[j] = __ldg((const float4*)(p1 + j * OO));
    const float4 bb0 = __ldg((const float4*)(b2 + (size_t)e0 * OO + o));
    const float4 bb1 = __ldg((const float4*)(b2 + (size_t)e1 * OO + o));

    // ---- finish fc1: fold 4 d-groups in-warp via shfl, then 8-deep smem ----
    #pragma unroll
    for (int off = 16; off >= 8; off >>= 1) {
        t.x += __shfl_xor_sync(0xFFFFFFFFu, t.x, off);
        t.y += __shfl_xor_sync(0xFFFFFFFFu, t.y, off);
        t.z += __shfl_xor_sync(0xFFFFFFFFu, t.z, off);
        t.w += __shfl_xor_sync(0xFFFFFFFFu, t.w, off);
    }
    if (lane < 8) *(float4*)&part[warp][lane * 4] = t;
    __syncthreads();

    // ---- broadcast this block's 32 h values into all 4 cluster CTAs' smem --
    if (tid < 32) {
        float sum = biasv;
        #pragma unroll
        for (int w = 0; w < 8; ++w) sum += part[w][tid];
        const float hv = gk * fmaxf(sum, 0.0f);
        const unsigned int la = smem_u32(&hs[k * HH + ch * 32 + tid]);
        #pragma unroll
        for (int r = 0; r < CLUSTER; ++r) dsmem_store(la, r, hv);
    }

    // ---- CLUSTER BARRIER: h now complete in every CTA's local smem ---------
    asm volatile("barrier.cluster.arrive.aligned;" ::: "memory");
    asm volatile("barrier.cluster.wait.aligned;"   ::: "memory");

    // ---- PHASE 2: h from LOCAL smem, w2/b2 from registers ------------------
    float4 acc = {0, 0, 0, 0};
    {
        const float4* h0p = (const float4*)(hs + s * 16);
        const float4* h1p = (const float4*)(hs + HH + s * 16);
        #pragma unroll
        for (int q = 0; q < 4; ++q) {
            float4 hq = h0p[q];
            fma4(acc, hq.x, w2r0[q * 4 + 0]);
            fma4(acc, hq.y, w2r0[q * 4 + 1]);
            fma4(acc, hq.z, w2r0[q * 4 + 2]);
            fma4(acc, hq.w, w2r0[q * 4 + 3]);
        }
        #pragma unroll
        for (int q = 0; q < 4; ++q) {
            float4 hq = h1p[q];
            fma4(acc, hq.x, w2r1[q * 4 + 0]);
            fma4(acc, hq.y, w2r1[q * 4 + 1]);
            fma4(acc, hq.z, w2r1[q * 4 + 2]);
            fma4(acc, hq.w, w2r1[q * 4 + 3]);
        }
    }

    // reduce across the 4 k-quarters (lanes 4g+s share a warp)
    #pragma unroll
    for (int off = 1; off <= 2; off <<= 1) {
        acc.x += __shfl_xor_sync(0xFFFFFFFFu, acc.x, off);
        acc.y += __shfl_xor_sync(0xFFFFFFFFu, acc.y, off);
        acc.z += __shfl_xor_sync(0xFFFFFFFFu, acc.z, off);
        acc.w += __shfl_xor_sync(0xFFFFFFFFu, acc.w, off);
    }

    if (g < ng && s == 0) {
        float4 r;
        r.x = acc.x + gk0 * bb0.x + gk1 * bb1.x;
        r.y = acc.y + gk0 * bb0.y + gk1 * bb1.y;
        r.z = acc.z + gk0 * bb0.z + gk1 * bb1.z;
        r.w = acc.w + gk0 * bb0.w + gk1 * bb1.w;
        *(float4*)(out + b * OO + o) = r;
    }
}

// Inputs: x, gate_w, gate_b, w1, b1, w2, b2. Output: f32 [32,1000]
extern "C" void kernel_launch(void* const* d_in, const int* in_sizes, int n_in,
                              void* d_out, int out_size) {
    const float* x  = (const float*)d_in[0];
    const float* gw = (const float*)d_in[1];
    const float* gb = (const float*)d_in[2];
    const float* w1 = (const float*)d_in[3];
    const float* b1 = (const float*)d_in[4];
    const float* w2 = (const float*)d_in[5];
    const float* b2 = (const float*)d_in[6];
    float* out = (float*)d_out;

    moe_fused<<<NBLK, NTHR>>>(x, gw, gb, w1, b1, w2, b2, out);
}